// round 2
// baseline (speedup 1.0000x reference)
#include <cuda_runtime.h>

// EdgesToGlobalsAggregator: segment-sum of edges [TOTAL_EDGES, 128] fp32 into
// [num_graphs, 128] fp32, with per-graph edge counts n_edge (prefix-summed on
// device so the kernel is fully general, though the bench uses uniform 2048).

#define MAX_GRAPHS 1024
#define D_FEAT 128
#define VEC (D_FEAT / 4)   // 32 float4 per row

__device__ int g_offsets[MAX_GRAPHS + 1];

// Single-block inclusive scan (Hillis-Steele) of n_edge -> exclusive offsets.
__global__ void scan_offsets_kernel(const int* __restrict__ n_edge, int num_graphs) {
    __shared__ int s[MAX_GRAPHS];
    int t = threadIdx.x;
    s[t] = (t < num_graphs) ? n_edge[t] : 0;
    __syncthreads();
    #pragma unroll
    for (int off = 1; off < MAX_GRAPHS; off <<= 1) {
        int v = (t >= off) ? s[t - off] : 0;
        __syncthreads();
        s[t] += v;
        __syncthreads();
    }
    if (t == 0) g_offsets[0] = 0;
    g_offsets[t + 1] = s[t];
}

__global__ __launch_bounds__(256, 4)
void segment_sum_kernel(const float4* __restrict__ edges, float4* __restrict__ out) {
    const int g    = blockIdx.x;
    const int lane = threadIdx.x & 31;   // float4 feature slot 0..31
    const int warp = threadIdx.x >> 5;   // row-slice 0..7

    const int start = g_offsets[g];
    const int nrows = g_offsets[g + 1] - start;

    const float4* __restrict__ base = edges + (size_t)start * VEC;

    float4 a0 = make_float4(0.f, 0.f, 0.f, 0.f);
    float4 a1 = make_float4(0.f, 0.f, 0.f, 0.f);
    float4 a2 = make_float4(0.f, 0.f, 0.f, 0.f);
    float4 a3 = make_float4(0.f, 0.f, 0.f, 0.f);

    int r = warp;
    // 4-way unrolled main loop: 4 independent LDG.128 in flight per iter.
    for (; r + 24 < nrows; r += 32) {
        float4 v0 = base[(size_t)(r)      * VEC + lane];
        float4 v1 = base[(size_t)(r + 8)  * VEC + lane];
        float4 v2 = base[(size_t)(r + 16) * VEC + lane];
        float4 v3 = base[(size_t)(r + 24) * VEC + lane];
        a0.x += v0.x; a0.y += v0.y; a0.z += v0.z; a0.w += v0.w;
        a1.x += v1.x; a1.y += v1.y; a1.z += v1.z; a1.w += v1.w;
        a2.x += v2.x; a2.y += v2.y; a2.z += v2.z; a2.w += v2.w;
        a3.x += v3.x; a3.y += v3.y; a3.z += v3.z; a3.w += v3.w;
    }
    // tail
    for (; r < nrows; r += 8) {
        float4 v = base[(size_t)r * VEC + lane];
        a0.x += v.x; a0.y += v.y; a0.z += v.z; a0.w += v.w;
    }

    a0.x += a1.x + a2.x + a3.x;
    a0.y += a1.y + a2.y + a3.y;
    a0.z += a1.z + a2.z + a3.z;
    a0.w += a1.w + a2.w + a3.w;

    __shared__ float4 sp[8][32];
    sp[warp][lane] = a0;
    __syncthreads();

    if (warp == 0) {
        float4 s = sp[0][lane];
        #pragma unroll
        for (int i = 1; i < 8; i++) {
            float4 v = sp[i][lane];
            s.x += v.x; s.y += v.y; s.z += v.z; s.w += v.w;
        }
        out[(size_t)g * VEC + lane] = s;
    }
}

extern "C" void kernel_launch(void* const* d_in, const int* in_sizes, int n_in,
                              void* d_out, int out_size) {
    const float* edges  = (const float*)d_in[0];
    const int*   n_edge = (const int*)d_in[1];
    const int num_graphs = in_sizes[1];          // 1024

    scan_offsets_kernel<<<1, MAX_GRAPHS>>>(n_edge, num_graphs);
    segment_sum_kernel<<<num_graphs, 256>>>((const float4*)edges, (float4*)d_out);
}

// round 3
// speedup vs baseline: 1.0202x; 1.0202x over previous
#include <cuda_runtime.h>

// EdgesToGlobalsAggregator: segment-sum of edges [TOTAL_EDGES, 128] fp32 into
// [num_graphs, 128] fp32. Fused single kernel: each block computes its own
// exclusive prefix of n_edge (4KB, L2-resident), then streams its segment.

#define D_FEAT 128
#define VEC (D_FEAT / 4)   // 32 float4 per row
#define NTHREADS 256

__global__ __launch_bounds__(NTHREADS, 4)
void segment_sum_fused_kernel(const float4* __restrict__ edges,
                              const int* __restrict__ n_edge,
                              int num_graphs,
                              float4* __restrict__ out) {
    const int g    = blockIdx.x;
    const int tid  = threadIdx.x;
    const int lane = tid & 31;   // float4 feature slot 0..31
    const int warp = tid >> 5;   // row-slice 0..7

    // ---- per-block exclusive prefix: start = sum(n_edge[0..g-1]), mine = n_edge[g]
    __shared__ int s_warp[8];
    __shared__ int s_start, s_mine;

    int local = 0;
    for (int i = tid; i < g; i += NTHREADS)
        local += __ldg(&n_edge[i]);
    #pragma unroll
    for (int off = 16; off > 0; off >>= 1)
        local += __shfl_down_sync(0xFFFFFFFFu, local, off);
    if (lane == 0) s_warp[warp] = local;
    __syncthreads();
    if (tid == 0) {
        int acc = 0;
        #pragma unroll
        for (int i = 0; i < 8; i++) acc += s_warp[i];
        s_start = acc;
        s_mine  = __ldg(&n_edge[g]);
    }
    __syncthreads();

    const int start = s_start;
    const int nrows = s_mine;

    const float4* __restrict__ base = edges + (size_t)start * VEC;

    float4 a0 = make_float4(0.f, 0.f, 0.f, 0.f);
    float4 a1 = make_float4(0.f, 0.f, 0.f, 0.f);
    float4 a2 = make_float4(0.f, 0.f, 0.f, 0.f);
    float4 a3 = make_float4(0.f, 0.f, 0.f, 0.f);

    int r = warp;
    // 4-way unrolled main loop: 4 independent streaming LDG.128 in flight.
    for (; r + 24 < nrows; r += 32) {
        float4 v0 = __ldcs(&base[(size_t)(r)      * VEC + lane]);
        float4 v1 = __ldcs(&base[(size_t)(r + 8)  * VEC + lane]);
        float4 v2 = __ldcs(&base[(size_t)(r + 16) * VEC + lane]);
        float4 v3 = __ldcs(&base[(size_t)(r + 24) * VEC + lane]);
        a0.x += v0.x; a0.y += v0.y; a0.z += v0.z; a0.w += v0.w;
        a1.x += v1.x; a1.y += v1.y; a1.z += v1.z; a1.w += v1.w;
        a2.x += v2.x; a2.y += v2.y; a2.z += v2.z; a2.w += v2.w;
        a3.x += v3.x; a3.y += v3.y; a3.z += v3.z; a3.w += v3.w;
    }
    // tail
    for (; r < nrows; r += 8) {
        float4 v = __ldcs(&base[(size_t)r * VEC + lane]);
        a0.x += v.x; a0.y += v.y; a0.z += v.z; a0.w += v.w;
    }

    a0.x += a1.x + a2.x + a3.x;
    a0.y += a1.y + a2.y + a3.y;
    a0.z += a1.z + a2.z + a3.z;
    a0.w += a1.w + a2.w + a3.w;

    __shared__ float4 sp[8][32];
    sp[warp][lane] = a0;
    __syncthreads();

    if (warp == 0) {
        float4 s = sp[0][lane];
        #pragma unroll
        for (int i = 1; i < 8; i++) {
            float4 v = sp[i][lane];
            s.x += v.x; s.y += v.y; s.z += v.z; s.w += v.w;
        }
        out[(size_t)g * VEC + lane] = s;
    }
}

extern "C" void kernel_launch(void* const* d_in, const int* in_sizes, int n_in,
                              void* d_out, int out_size) {
    const float* edges  = (const float*)d_in[0];
    const int*   n_edge = (const int*)d_in[1];
    const int num_graphs = in_sizes[1];          // 1024

    segment_sum_fused_kernel<<<num_graphs, NTHREADS>>>(
        (const float4*)edges, n_edge, num_graphs, (float4*)d_out);
}